// round 3
// baseline (speedup 1.0000x reference)
#include <cuda_runtime.h>

// Problem constants (fixed by the reference: B=4, C=8, H=W=1024, R=1 cross kernel, wrap pad)
constexpr int Hh = 1024;
constexpr int Ww = 1024;
constexpr int PLANE = Hh * Ww;          // 1,048,576
constexpr int W4 = Ww / 4;              // 256 float4 per row

// Accurate fp32 exp (Cody-Waite reduction + cephes degree-6 poly, ~1 ulp).
// Immune to -use_fast_math rewriting of expf; only FMAs + one int bit-trick scale.
__device__ __forceinline__ float exp_acc(float x) {
    x = fminf(fmaxf(x, -87.3f), 88.0f);
    float n = rintf(x * 1.44269504088896341f);
    float r = fmaf(n, -0.693359375f, x);        // Cody-Waite hi
    r = fmaf(n, 2.12194440e-4f, r);             // Cody-Waite lo
    float rr = r * r;
    float y = 1.9875691500e-4f;
    y = fmaf(y, r, 1.3981999507e-3f);
    y = fmaf(y, r, 8.3334519073e-3f);
    y = fmaf(y, r, 4.1665795894e-2f);
    y = fmaf(y, r, 1.6666665459e-1f);
    y = fmaf(y, r, 5.0000001201e-1f);
    y = fmaf(y, rr, r);
    y = y + 1.0f;
    float sc = __int_as_float(((int)n + 127) << 23);
    return y * sc;
}

__device__ __forceinline__ float flip_one(float s, float J, float bf, float r, bool drop) {
    float de = 2.0f * s * J;
    bool flip;
    if (de <= 0.0f) {
        flip = drop;                            // p = 1, rand in [0,1) < 1 always
    } else {
        float p = exp_acc(-de * bf);
        flip = (r < p) && drop;
    }
    return flip ? -s : s;
}

__device__ __forceinline__ float4 ld_cs4(const float* p) {
    return __ldcs(reinterpret_cast<const float4*>(p));
}
__device__ __forceinline__ void st_cs4(float* p, float4 v) {
    __stcs(reinterpret_cast<float4*>(p), v);
}

__global__ __launch_bounds__(256, 7) void ising_step_kernel(
    const float* __restrict__ x,      // (4, 9, 1024, 1024): s = ch 0..7, b = ch 8
    const float* __restrict__ rnd,    // (4, 8, 1024, 1024)
    const float* __restrict__ drop,   // (1024, 1024)
    float* __restrict__ out)          // (4, 9, 1024, 1024)
{
    int tid = blockIdx.x * blockDim.x + threadIdx.x;   // 0 .. 4*1024*256-1
    int lane = threadIdx.x & 31;
    int w4 = tid & (W4 - 1);
    int h  = (tid >> 8) & (Hh - 1);
    int b  = tid >> 18;
    int w  = w4 * 4;

    int rowc = h * Ww + w;                                  // this thread's 4 pixels
    int du = (((h + Hh - 1) & (Hh - 1)) - h) * Ww;          // relative offset: up row (wrap)
    int dd = (((h + 1) & (Hh - 1)) - h) * Ww;               // relative offset: down row (wrap)
    int dl = ((w + Ww - 1) & (Ww - 1)) - w;                 // relative: left-of-lane0 pixel (wrap)
    int dr_ = ((w + 4) & (Ww - 1)) - w;                     // relative: right-of-lane31 pixel (wrap)

    const float* xb = x + b * 9 * PLANE + rowc;

    // Pass 1: accumulate J (channel-summed cross-neighbor sum). Left/right
    // neighbors come from warp shuffles of the center vector; only lanes 0/31
    // need a scalar load (warp spans 128 contiguous pixels).
    float4 J = make_float4(0.f, 0.f, 0.f, 0.f);
    {
        const float* sp = xb;
        #pragma unroll
        for (int c = 0; c < 8; c++, sp += PLANE) {
            float4 cc = *reinterpret_cast<const float4*>(sp);   // stays in L1 for pass 2
            float4 up = ld_cs4(sp + du);                        // read-once in this thread
            float4 dn = ld_cs4(sp + dd);
            float lf = __shfl_up_sync(0xffffffffu, cc.w, 1);
            float rt = __shfl_down_sync(0xffffffffu, cc.x, 1);
            if (lane == 0)  lf = __ldcs(sp + dl);
            if (lane == 31) rt = __ldcs(sp + dr_);
            J.x += (up.x + dn.x) + (lf   + cc.y);
            J.y += (up.y + dn.y) + (cc.x + cc.z);
            J.z += (up.z + dn.z) + (cc.y + cc.w);
            J.w += (up.w + dn.w) + (cc.z + rt);
        }
    }

    // Field b and dropout mask for these 4 pixels
    float4 bf = *reinterpret_cast<const float4*>(xb + 8 * PLANE);
    float4 dv = ld_cs4(drop + rowc);
    bool d0 = dv.x > 0.5f, d1 = dv.y > 0.5f, d2 = dv.z > 0.5f, d3 = dv.w > 0.5f;

    float* ob = out + b * 9 * PLANE + rowc;
    st_cs4(ob + 8 * PLANE, bf);                 // pass-through channel 8 (the field)

    const float* rb = rnd + b * 8 * PLANE + rowc;
    {
        const float* sp = xb;
        float* op = ob;
        const float* rp = rb;
        #pragma unroll
        for (int c = 0; c < 8; c++, sp += PLANE, op += PLANE, rp += PLANE) {
            float4 cc = *reinterpret_cast<const float4*>(sp);   // L1 hit (loaded in pass 1)
            float4 rv = ld_cs4(rp);                             // read-once stream
            float4 o;
            o.x = flip_one(cc.x, J.x, bf.x, rv.x, d0);
            o.y = flip_one(cc.y, J.y, bf.y, rv.y, d1);
            o.z = flip_one(cc.z, J.z, bf.z, rv.z, d2);
            o.w = flip_one(cc.w, J.w, bf.w, rv.w, d3);
            st_cs4(op, o);                                      // write-once: don't pollute L2
        }
    }
}

extern "C" void kernel_launch(void* const* d_in, const int* in_sizes, int n_in,
                              void* d_out, int out_size) {
    const float* x    = (const float*)d_in[0];   // (4,9,1024,1024)
    const float* rnd  = (const float*)d_in[1];   // (4,8,1024,1024)
    const float* drop = (const float*)d_in[2];   // (1024,1024)
    // d_in[3] = nn_kernel: fixed cross structure, baked into the kernel
    float* out = (float*)d_out;

    int total_threads = 4 * Hh * W4;             // 1,048,576
    int block = 256;
    int grid = total_threads / block;            // 4096
    ising_step_kernel<<<grid, block>>>(x, rnd, drop, out);
}